// round 1
// baseline (speedup 1.0000x reference)
#include <cuda_runtime.h>

// ChamferLossKL: bs=8, n=2048, d=4.
// KL(a_i || b_j) = 0.5 * (S_ij + sb_j - sa_i - d)
//   where S_ij = cb_j + sum_d A_id*iv_jd + sum_d mu_a_id * w_jd
//   A = exp(la) + mu_a^2, iv = exp(-lb), w = -2*mu_b*iv, cb = sum mu_b^2*iv
// loss = sum_j min_i KL + sum_i min_j KL
//
// Role 0 (min over j for each i): stream FB, seed acc with +csb_j (csb=cb+sb)
//   -> minv tracks (S + sb); result = 0.5*minv - 0.5*(sa_i + 4)
// Role 1 (min over i for each j): stream FA, seed acc with -sa_i
//   -> minv tracks (S - cb - sa); result = 0.5*minv + 0.5*(csb_j - 4)
// Both: result = 0.5*minv - 0.5*s*selfc - 2, s = +1 (role0) / -1 (role1),
// and acc seed = s * stream_f2.x.  One kernel, two roles via blockIdx.z.

#define NB 8
#define NP 2048
#define TILE 128

// Scratch (no allocation allowed in kernel_launch)
__device__ float4 g_FA[NB * NP * 3];   // {A[4]}, {mu_a[4]}, {sa,0,0,0}
__device__ float4 g_FB[NB * NP * 3];   // {iv[4]}, {w[4]},   {csb,0,0,0}
__device__ float  g_min[2 * NB * NP];  // per-point min-KL, role-major

__global__ void ck_precompute(const float* __restrict__ mu_p,
                              const float* __restrict__ lv_p,
                              const float* __restrict__ mu_g,
                              const float* __restrict__ lv_g) {
    int idx = blockIdx.x * blockDim.x + threadIdx.x;
    if (idx >= NB * NP) return;
    float4 mp = reinterpret_cast<const float4*>(mu_p)[idx];
    float4 lp = reinterpret_cast<const float4*>(lv_p)[idx];
    float4 mg = reinterpret_cast<const float4*>(mu_g)[idx];
    float4 lg = reinterpret_cast<const float4*>(lv_g)[idx];

    // FA: preds side
    float4 A;
    A.x = expf(lp.x) + mp.x * mp.x;
    A.y = expf(lp.y) + mp.y * mp.y;
    A.z = expf(lp.z) + mp.z * mp.z;
    A.w = expf(lp.w) + mp.w * mp.w;
    float sa = lp.x + lp.y + lp.z + lp.w;
    g_FA[idx * 3 + 0] = A;
    g_FA[idx * 3 + 1] = mp;
    g_FA[idx * 3 + 2] = make_float4(sa, 0.f, 0.f, 0.f);

    // FB: gts side
    float4 iv;
    iv.x = expf(-lg.x); iv.y = expf(-lg.y); iv.z = expf(-lg.z); iv.w = expf(-lg.w);
    float4 w;
    w.x = -2.f * mg.x * iv.x;
    w.y = -2.f * mg.y * iv.y;
    w.z = -2.f * mg.z * iv.z;
    w.w = -2.f * mg.w * iv.w;
    float cb = mg.x * mg.x * iv.x + mg.y * mg.y * iv.y
             + mg.z * mg.z * iv.z + mg.w * mg.w * iv.w;
    float sb = lg.x + lg.y + lg.z + lg.w;
    g_FB[idx * 3 + 0] = iv;
    g_FB[idx * 3 + 1] = w;
    g_FB[idx * 3 + 2] = make_float4(cb + sb, 0.f, 0.f, 0.f);
}

__global__ __launch_bounds__(TILE) void ck_chamfer_min() {
    int tid  = threadIdx.x;
    int b    = blockIdx.y;
    int role = blockIdx.z;

    const float4* selfArr = role ? g_FB : g_FA;
    const float4* strArr  = role ? g_FA : g_FB;
    float s = role ? -1.0f : 1.0f;

    int self_i = blockIdx.x * TILE + tid;
    int sbase  = (b * NP + self_i) * 3;
    float4 p0 = selfArr[sbase + 0];
    float4 p1 = selfArr[sbase + 1];
    float  selfc = selfArr[sbase + 2].x;
    float a0 = p0.x, a1 = p0.y, a2 = p0.z, a3 = p0.w;
    float m0 = p1.x, m1 = p1.y, m2 = p1.z, m3 = p1.w;

    __shared__ float4 sm[TILE * 3];
    float minv = 3.0e38f;

    for (int t = 0; t < NP; t += TILE) {
        int gb = (b * NP + t) * 3;
        __syncthreads();
        sm[tid]            = strArr[gb + tid];
        sm[tid + TILE]     = strArr[gb + tid + TILE];
        sm[tid + 2 * TILE] = strArr[gb + tid + 2 * TILE];
        __syncthreads();
#pragma unroll 4
        for (int jj = 0; jj < TILE; jj++) {
            float4 f0 = sm[jj * 3 + 0];
            float4 f1 = sm[jj * 3 + 1];
            float  c  = sm[jj * 3 + 2].x;
            // two parallel chains to shorten the dependency chain
            float acc0 = s * c;
            acc0 = fmaf(a0, f0.x, acc0);
            acc0 = fmaf(a1, f0.y, acc0);
            acc0 = fmaf(a2, f0.z, acc0);
            acc0 = fmaf(a3, f0.w, acc0);
            float acc1 = m0 * f1.x;
            acc1 = fmaf(m1, f1.y, acc1);
            acc1 = fmaf(m2, f1.z, acc1);
            acc1 = fmaf(m3, f1.w, acc1);
            minv = fminf(minv, acc0 + acc1);
        }
    }

    g_min[(role * NB + b) * NP + self_i] = 0.5f * minv - 0.5f * s * selfc - 2.0f;
}

__global__ void ck_reduce(float* __restrict__ out) {
    int b = blockIdx.x;
    int tid = threadIdx.x;  // 256 threads
    const float* mA = &g_min[b * NP];
    const float* mB = &g_min[(NB + b) * NP];
    float sum = 0.f;
    for (int i = tid; i < NP; i += 256) sum += mA[i] + mB[i];
    __shared__ float red[256];
    red[tid] = sum;
    __syncthreads();
    for (int st = 128; st > 0; st >>= 1) {
        if (tid < st) red[tid] += red[tid + st];
        __syncthreads();
    }
    if (tid == 0) out[b] = red[0];
}

extern "C" void kernel_launch(void* const* d_in, const int* in_sizes, int n_in,
                              void* d_out, int out_size) {
    const float* mu_p = (const float*)d_in[0];
    const float* lv_p = (const float*)d_in[1];
    const float* mu_g = (const float*)d_in[2];
    const float* lv_g = (const float*)d_in[3];
    float* out = (float*)d_out;

    ck_precompute<<<(NB * NP + 255) / 256, 256>>>(mu_p, lv_p, mu_g, lv_g);

    dim3 grid(NP / TILE, NB, 2);   // 16 x 8 x 2 = 256 CTAs
    ck_chamfer_min<<<grid, TILE>>>();

    ck_reduce<<<NB, 256>>>(out);
}

// round 2
// speedup vs baseline: 1.5410x; 1.5410x over previous
#include <cuda_runtime.h>

// ChamferLossKL: bs=8, n=2048, d=4.
// KL(a_i || b_j) = 0.5*(S_ij + sb_j - sa_i - 4),
//   S_ij = cb_j + sum_d A_id*iv_jd + sum_d mu_a_id * w_jd
//   A = exp(la)+mu_a^2, iv = exp(-lb), w = -2*mu_b*iv, cb = sum mu_b^2*iv
//
// Pre-signed constants: preds c = -sa, gts c = +(cb+sb) = +csb.
// Role 0 (per-pred min over gts):  stream gts,  self preds:
//   min_j (csb_j + A.iv + m.w);  res = 0.5*min + 0.5*(-sa_i) - 2
// Role 1 (per-gt min over preds): stream preds, self gts:
//   min_i (-sa_i + iv.A + w.m);  res = 0.5*min + 0.5*(csb_j) - 2
// Same inner loop, same epilogue.  Stream arrays packed by j-pair for
// fma.rn.f32x2: per pair of j, 5 float4 = {iv0/iv1 pairs, iv2/iv3,
// w0/w1, w2/w3, (c,c',pad,pad)}.

#define NB 8
#define NP 2048
#define NPAIR (NP/2)

// ---- packed f32x2 helpers ----
__device__ __forceinline__ unsigned long long ffma2(unsigned long long a,
                                                    unsigned long long b,
                                                    unsigned long long c) {
    unsigned long long d;
    asm("fma.rn.f32x2 %0, %1, %2, %3;" : "=l"(d) : "l"(a), "l"(b), "l"(c));
    return d;
}
__device__ __forceinline__ unsigned long long packdup(float x) {
    unsigned long long d;
    asm("mov.b64 %0, {%1, %1};" : "=l"(d) : "f"(x));
    return d;
}
__device__ __forceinline__ void unpk(unsigned long long v, float& lo, float& hi) {
    asm("mov.b64 {%0, %1}, %2;" : "=f"(lo), "=f"(hi) : "l"(v));
}
__device__ __forceinline__ void lds_v2(unsigned long long& a, unsigned long long& b,
                                       unsigned int addr) {
    asm volatile("ld.shared.v2.u64 {%0, %1}, [%2];" : "=l"(a), "=l"(b) : "r"(addr));
}
__device__ __forceinline__ unsigned long long lds_1(unsigned int addr) {
    unsigned long long a;
    asm volatile("ld.shared.u64 %0, [%1];" : "=l"(a) : "r"(addr));
    return a;
}

// ---- scratch (no allocation allowed) ----
__device__ float4 g_SA[NB * NP * 3];        // self preds: {A}, {mu}, {-sa,..}
__device__ float4 g_SB[NB * NP * 3];        // self gts:   {iv}, {w}, {+csb,..}
__device__ float4 g_PA[NB * NPAIR * 5];     // stream preds, j-pair packed
__device__ float4 g_PB[NB * NPAIR * 5];     // stream gts,  j-pair packed
__device__ float  g_part[2 * NB * 4 * NP];  // partial mins per quarter

__global__ void ck_precompute(const float* __restrict__ mu_p,
                              const float* __restrict__ lv_p,
                              const float* __restrict__ mu_g,
                              const float* __restrict__ lv_g) {
    int idx = blockIdx.x * blockDim.x + threadIdx.x;
    if (idx >= NB * NP) return;
    int b = idx / NP, j = idx % NP;
    int p = j >> 1, L = j & 1;

    float4 mp = reinterpret_cast<const float4*>(mu_p)[idx];
    float4 lp = reinterpret_cast<const float4*>(lv_p)[idx];
    float4 mg = reinterpret_cast<const float4*>(mu_g)[idx];
    float4 lg = reinterpret_cast<const float4*>(lv_g)[idx];

    // preds side: A = exp(la)+mu^2, c = -sa
    float4 A;
    A.x = expf(lp.x) + mp.x * mp.x;
    A.y = expf(lp.y) + mp.y * mp.y;
    A.z = expf(lp.z) + mp.z * mp.z;
    A.w = expf(lp.w) + mp.w * mp.w;
    float ca = -(lp.x + lp.y + lp.z + lp.w);
    g_SA[idx * 3 + 0] = A;
    g_SA[idx * 3 + 1] = mp;
    g_SA[idx * 3 + 2] = make_float4(ca, 0.f, 0.f, 0.f);

    float* PA = reinterpret_cast<float*>(g_PA) + (b * NPAIR + p) * 20;
    PA[0 + L] = A.x;  PA[2 + L] = A.y;  PA[4 + L] = A.z;  PA[6 + L] = A.w;
    PA[8 + L] = mp.x; PA[10 + L] = mp.y; PA[12 + L] = mp.z; PA[14 + L] = mp.w;
    PA[16 + L] = ca;

    // gts side: iv = exp(-lb), w = -2*mu*iv, c = cb+sb
    float4 iv;
    iv.x = expf(-lg.x); iv.y = expf(-lg.y); iv.z = expf(-lg.z); iv.w = expf(-lg.w);
    float4 w;
    w.x = -2.f * mg.x * iv.x; w.y = -2.f * mg.y * iv.y;
    w.z = -2.f * mg.z * iv.z; w.w = -2.f * mg.w * iv.w;
    float cb = mg.x * mg.x * iv.x + mg.y * mg.y * iv.y
             + mg.z * mg.z * iv.z + mg.w * mg.w * iv.w;
    float cg = cb + lg.x + lg.y + lg.z + lg.w;
    g_SB[idx * 3 + 0] = iv;
    g_SB[idx * 3 + 1] = w;
    g_SB[idx * 3 + 2] = make_float4(cg, 0.f, 0.f, 0.f);

    float* PB = reinterpret_cast<float*>(g_PB) + (b * NPAIR + p) * 20;
    PB[0 + L] = iv.x; PB[2 + L] = iv.y; PB[4 + L] = iv.z; PB[6 + L] = iv.w;
    PB[8 + L] = w.x;  PB[10 + L] = w.y; PB[12 + L] = w.z; PB[14 + L] = w.w;
    PB[16 + L] = cg;
}

// grid: (16 i-tiles, 8 batches, role*4 + jquarter), block 128.
// Each CTA: 128 self points x 512 stream points (one quarter).
__global__ __launch_bounds__(128) void ck_chamfer_min() {
    int tid  = threadIdx.x;
    int b    = blockIdx.y;
    int role = blockIdx.z >> 2;
    int jq   = blockIdx.z & 3;

    const float4* selfArr = role ? g_SB : g_SA;
    const float4* strArr  = role ? g_PA : g_PB;

    int self_i = blockIdx.x * 128 + tid;
    int sbase  = (b * NP + self_i) * 3;
    float4 p0 = selfArr[sbase + 0];
    float4 p1 = selfArr[sbase + 1];
    float  self_c = selfArr[sbase + 2].x;

    unsigned long long cA0 = packdup(p0.x), cA1 = packdup(p0.y);
    unsigned long long cA2 = packdup(p0.z), cA3 = packdup(p0.w);
    unsigned long long cM0 = packdup(p1.x), cM1 = packdup(p1.y);
    unsigned long long cM2 = packdup(p1.z), cM3 = packdup(p1.w);

    __shared__ float4 sm[64 * 5];  // 64 j-pairs * 80B
    unsigned int saddr0 = (unsigned int)__cvta_generic_to_shared(sm);

    float minv0 = 3.0e38f, minv1 = 3.0e38f;

    for (int t = 0; t < 4; t++) {  // 4 tiles of 64 pairs = 512 j
        int pair0 = b * NPAIR + jq * 256 + t * 64;
        const float4* pk = &strArr[pair0 * 5];
        __syncthreads();
#pragma unroll
        for (int k = 0; k < 3; k++) {
            int idx = tid + k * 128;
            if (idx < 320) sm[idx] = pk[idx];
        }
        __syncthreads();

        unsigned int ad = saddr0;
#pragma unroll 4
        for (int p = 0; p < 64; p++) {
            unsigned long long q0l, q0h, q1l, q1h, q2l, q2h, q3l, q3h;
            lds_v2(q0l, q0h, ad);
            lds_v2(q1l, q1h, ad + 16);
            lds_v2(q2l, q2h, ad + 32);
            lds_v2(q3l, q3h, ad + 48);
            unsigned long long acc = lds_1(ad + 64);
            acc = ffma2(cA0, q0l, acc);
            acc = ffma2(cA1, q0h, acc);
            acc = ffma2(cA2, q1l, acc);
            acc = ffma2(cA3, q1h, acc);
            acc = ffma2(cM0, q2l, acc);
            acc = ffma2(cM1, q2h, acc);
            acc = ffma2(cM2, q3l, acc);
            acc = ffma2(cM3, q3h, acc);
            float vlo, vhi;
            unpk(acc, vlo, vhi);
            minv0 = fminf(minv0, vlo);
            minv1 = fminf(minv1, vhi);
            ad += 80;
        }
    }

    float minv = fminf(minv0, minv1);
    float res = 0.5f * minv + 0.5f * self_c - 2.0f;
    g_part[(role * NB + b) * 4 * NP + jq * NP + self_i] = res;
}

__global__ void ck_reduce(float* __restrict__ out) {
    int b = blockIdx.x;
    int tid = threadIdx.x;  // 256
    const float* r0 = &g_part[(0 * NB + b) * 4 * NP];
    const float* r1 = &g_part[(1 * NB + b) * 4 * NP];
    float sum = 0.f;
    for (int i = tid; i < NP; i += 256) {
        float m0 = fminf(fminf(r0[i], r0[NP + i]), fminf(r0[2 * NP + i], r0[3 * NP + i]));
        float m1 = fminf(fminf(r1[i], r1[NP + i]), fminf(r1[2 * NP + i], r1[3 * NP + i]));
        sum += m0 + m1;
    }
    __shared__ float red[256];
    red[tid] = sum;
    __syncthreads();
    for (int st = 128; st > 0; st >>= 1) {
        if (tid < st) red[tid] += red[tid + st];
        __syncthreads();
    }
    if (tid == 0) out[b] = red[0];
}

extern "C" void kernel_launch(void* const* d_in, const int* in_sizes, int n_in,
                              void* d_out, int out_size) {
    const float* mu_p = (const float*)d_in[0];
    const float* lv_p = (const float*)d_in[1];
    const float* mu_g = (const float*)d_in[2];
    const float* lv_g = (const float*)d_in[3];
    float* out = (float*)d_out;

    ck_precompute<<<(NB * NP + 255) / 256, 256>>>(mu_p, lv_p, mu_g, lv_g);

    dim3 grid(NP / 128, NB, 8);  // 16 x 8 x (2 roles * 4 j-quarters) = 1024 CTAs
    ck_chamfer_min<<<grid, 128>>>();

    ck_reduce<<<NB, 256>>>(out);
}

// round 3
// speedup vs baseline: 2.0555x; 1.3339x over previous
#include <cuda_runtime.h>
#include <float.h>

// ChamferLossKL: bs=8, n=2048, d=4 — role-deduped single-pass.
// S_ij = sum_d A_id*iv_jd + sum_d mu_id*w_jd   (computed ONCE per pair)
//   A = exp(la)+mu_a^2, iv = exp(-lb), w = -2*mu_b*iv
// KL_ij = 0.5*(S + cb_j + sb_j - sa_i - 4) = 0.5*(S + csb_j + ca_i) - 2
//   with csb = cb+sb (per gt j), ca = -sa (per pred i)
// rowmin_i = min_j (S + csb_j)  -> rowres_i = 0.5*rowmin + 0.5*ca_i - 2
// colmin_j = min_i (S + ca_i)   -> colres_j = 0.5*colmin + 0.5*csb_j - 2
// loss_b = sum_i rowres + sum_j colres

#define NB 8
#define NP 2048
#define NPAIR 1024          // j-pairs per batch
#define ITILE 128           // i per CTA
#define NITILE (NP/ITILE)   // 16
#define CHJ 256             // j per chunk
#define CHP (CHJ/2)         // 128 pairs per chunk
#define NCH (NP/CHJ)        // 8
#define NGRP (CHP/32)       // 4 groups of 32 pairs

typedef unsigned long long ull;

// ---- packed f32x2 helpers ----
__device__ __forceinline__ ull ffma2(ull a, ull b, ull c) {
    ull d; asm("fma.rn.f32x2 %0, %1, %2, %3;" : "=l"(d) : "l"(a), "l"(b), "l"(c));
    return d;
}
__device__ __forceinline__ ull fmul2(ull a, ull b) {
    ull d; asm("mul.rn.f32x2 %0, %1, %2;" : "=l"(d) : "l"(a), "l"(b));
    return d;
}
__device__ __forceinline__ ull fadd2(ull a, ull b) {
    ull d; asm("add.rn.f32x2 %0, %1, %2;" : "=l"(d) : "l"(a), "l"(b));
    return d;
}
__device__ __forceinline__ ull packdup(float x) {
    ull d; asm("mov.b64 %0, {%1, %1};" : "=l"(d) : "f"(x));
    return d;
}
__device__ __forceinline__ ull pk(float lo, float hi) {
    ull d; asm("mov.b64 %0, {%1, %2};" : "=l"(d) : "f"(lo), "f"(hi));
    return d;
}
__device__ __forceinline__ void unpk(ull v, float& lo, float& hi) {
    asm("mov.b64 {%0, %1}, %2;" : "=f"(lo), "=f"(hi) : "l"(v));
}
__device__ __forceinline__ ull min2(ull a, ull b) {
    float al, ah, bl, bh;
    unpk(a, al, ah); unpk(b, bl, bh);
    return pk(fminf(al, bl), fminf(ah, bh));
}
__device__ __forceinline__ void lds_v2(ull& a, ull& b, unsigned int addr) {
    asm volatile("ld.shared.v2.u64 {%0, %1}, [%2];" : "=l"(a), "=l"(b) : "r"(addr));
}
__device__ __forceinline__ ull lds_1(unsigned int addr) {
    ull a; asm volatile("ld.shared.u64 %0, [%1];" : "=l"(a) : "r"(addr));
    return a;
}

// butterfly transpose-min step: after all 5 steps, lane L holds
// min over 32 lanes of that lane's original cv[L].
template<int M, int H>
__device__ __forceinline__ void bstep(ull* cv, int lane) {
    bool up = (lane & M) != 0;
#pragma unroll
    for (int k = 0; k < H; k++) {
        ull sb = up ? cv[k] : cv[k + H];     // send the half we don't keep
        ull rc = __shfl_xor_sync(0xffffffffu, sb, M);
        ull kp = up ? cv[k + H] : cv[k];     // keep our half
        cv[k] = min2(kp, rc);
    }
}

// ---- scratch ----
__device__ ull    g_colpart[NB * NITILE * NPAIR];  // 1 MB packed col-min partials
__device__ float  g_rowpart[NB * NCH * NP];        // 512 KB row-min partials (affine applied)
__device__ float2 g_csb[NB * NPAIR];               // csb pairs for reduce

// grid (NITILE, NB, NCH), block 128. CTA: 128 i x 256 j, each pair ONCE.
__global__ __launch_bounds__(128, 1) void ck_main(const float* __restrict__ mu_p,
                                                  const float* __restrict__ lv_p,
                                                  const float* __restrict__ mu_g,
                                                  const float* __restrict__ lv_g) {
    __shared__ float4 s_stream[CHP * 5];  // 128 pairs * 80B = 10 KB
    __shared__ ull    s_col[4 * CHP];     // 4 warps * 128 pairs = 4 KB

    int tid  = threadIdx.x;
    int lane = tid & 31;
    int w    = tid >> 5;
    int b     = blockIdx.y;
    int itile = blockIdx.x;
    int ch    = blockIdx.z;

    // ---- self coefficients (preds, one i per thread) ----
    int i = itile * ITILE + tid;
    float4 mp = reinterpret_cast<const float4*>(mu_p)[b * NP + i];
    float4 lp = reinterpret_cast<const float4*>(lv_p)[b * NP + i];
    float Ax = expf(lp.x) + mp.x * mp.x;
    float Ay = expf(lp.y) + mp.y * mp.y;
    float Az = expf(lp.z) + mp.z * mp.z;
    float Aw = expf(lp.w) + mp.w * mp.w;
    float ca = -(lp.x + lp.y + lp.z + lp.w);
    ull cA0 = packdup(Ax), cA1 = packdup(Ay), cA2 = packdup(Az), cA3 = packdup(Aw);
    ull cM0 = packdup(mp.x), cM1 = packdup(mp.y), cM2 = packdup(mp.z), cM3 = packdup(mp.w);
    ull negsa2 = packdup(ca);

    // ---- stream prep (gts): thread t builds pair t of the chunk ----
    {
        int j0 = ch * CHJ + 2 * tid;
        float4 mg0 = reinterpret_cast<const float4*>(mu_g)[b * NP + j0];
        float4 lg0 = reinterpret_cast<const float4*>(lv_g)[b * NP + j0];
        float4 mg1 = reinterpret_cast<const float4*>(mu_g)[b * NP + j0 + 1];
        float4 lg1 = reinterpret_cast<const float4*>(lv_g)[b * NP + j0 + 1];
        float4 iv0, iv1, w0, w1;
        iv0.x = expf(-lg0.x); iv0.y = expf(-lg0.y); iv0.z = expf(-lg0.z); iv0.w = expf(-lg0.w);
        iv1.x = expf(-lg1.x); iv1.y = expf(-lg1.y); iv1.z = expf(-lg1.z); iv1.w = expf(-lg1.w);
        w0.x = -2.f * mg0.x * iv0.x; w0.y = -2.f * mg0.y * iv0.y;
        w0.z = -2.f * mg0.z * iv0.z; w0.w = -2.f * mg0.w * iv0.w;
        w1.x = -2.f * mg1.x * iv1.x; w1.y = -2.f * mg1.y * iv1.y;
        w1.z = -2.f * mg1.z * iv1.z; w1.w = -2.f * mg1.w * iv1.w;
        float csb0 = mg0.x * mg0.x * iv0.x + mg0.y * mg0.y * iv0.y
                   + mg0.z * mg0.z * iv0.z + mg0.w * mg0.w * iv0.w
                   + lg0.x + lg0.y + lg0.z + lg0.w;
        float csb1 = mg1.x * mg1.x * iv1.x + mg1.y * mg1.y * iv1.y
                   + mg1.z * mg1.z * iv1.z + mg1.w * mg1.w * iv1.w
                   + lg1.x + lg1.y + lg1.z + lg1.w;
        s_stream[tid * 5 + 0] = make_float4(iv0.x, iv1.x, iv0.y, iv1.y);
        s_stream[tid * 5 + 1] = make_float4(iv0.z, iv1.z, iv0.w, iv1.w);
        s_stream[tid * 5 + 2] = make_float4(w0.x, w1.x, w0.y, w1.y);
        s_stream[tid * 5 + 3] = make_float4(w0.z, w1.z, w0.w, w1.w);
        s_stream[tid * 5 + 4] = make_float4(csb0, csb1, 0.f, 0.f);
        if (itile == 0)
            g_csb[b * NPAIR + ch * CHP + tid] = make_float2(csb0, csb1);
    }
    __syncthreads();

    unsigned int sbase = (unsigned int)__cvta_generic_to_shared(s_stream);
    float minr0 = FLT_MAX, minr1 = FLT_MAX;

    for (int g = 0; g < NGRP; g++) {
        ull cv[32];
        unsigned int ad = sbase + g * 32 * 80;
#pragma unroll
        for (int p = 0; p < 32; p++) {
            ull q0, q1, q2, q3, r0, r1, r2, r3;
            lds_v2(q0, q1, ad);
            lds_v2(q2, q3, ad + 16);
            lds_v2(r0, r1, ad + 32);
            lds_v2(r2, r3, ad + 48);
            ull csb = lds_1(ad + 64);
            ull acc = fmul2(cA0, q0);
            acc = ffma2(cA1, q1, acc);
            acc = ffma2(cA2, q2, acc);
            acc = ffma2(cA3, q3, acc);
            acc = ffma2(cM0, r0, acc);
            acc = ffma2(cM1, r1, acc);
            acc = ffma2(cM2, r2, acc);
            acc = ffma2(cM3, r3, acc);
            ull rowv = fadd2(acc, csb);
            float lo, hi; unpk(rowv, lo, hi);
            minr0 = fminf(minr0, lo);
            minr1 = fminf(minr1, hi);
            cv[p] = fadd2(acc, negsa2);
            ad += 80;
        }
        // cross-lane (over 32 i) min-transpose: lane L ends owning j-pair L of group
        bstep<16, 16>(cv, lane);
        bstep<8, 8>(cv, lane);
        bstep<4, 4>(cv, lane);
        bstep<2, 2>(cv, lane);
        bstep<1, 1>(cv, lane);
        s_col[w * CHP + g * 32 + lane] = cv[0];
    }

    // row result (affine is monotone: apply now, min partials later)
    float rres = 0.5f * fminf(minr0, minr1) + 0.5f * ca - 2.0f;
    g_rowpart[(b * NCH + ch) * NP + i] = rres;

    __syncthreads();
    // combine 4 warps' col partials -> global per-(itile) partial
    {
        int e = tid;  // 0..127 local pairs
        ull m = min2(min2(s_col[e], s_col[CHP + e]),
                     min2(s_col[2 * CHP + e], s_col[3 * CHP + e]));
        g_colpart[(b * NITILE + itile) * NPAIR + ch * CHP + e] = m;
    }
}

__global__ void ck_reduce(float* __restrict__ out) {
    int b = blockIdx.x;
    int tid = threadIdx.x;  // 256
    float sum = 0.f;
    for (int i = tid; i < NP; i += 256) {
        float m = g_rowpart[(b * NCH + 0) * NP + i];
#pragma unroll
        for (int c = 1; c < NCH; c++)
            m = fminf(m, g_rowpart[(b * NCH + c) * NP + i]);
        sum += m;
    }
    for (int e = tid; e < NPAIR; e += 256) {
        ull m = g_colpart[(b * NITILE + 0) * NPAIR + e];
#pragma unroll
        for (int it = 1; it < NITILE; it++)
            m = min2(m, g_colpart[(b * NITILE + it) * NPAIR + e]);
        float lo, hi; unpk(m, lo, hi);
        float2 cs = g_csb[b * NPAIR + e];
        sum += 0.5f * lo + 0.5f * cs.x - 2.0f;
        sum += 0.5f * hi + 0.5f * cs.y - 2.0f;
    }
    __shared__ float red[256];
    red[tid] = sum;
    __syncthreads();
    for (int st = 128; st > 0; st >>= 1) {
        if (tid < st) red[tid] += red[tid + st];
        __syncthreads();
    }
    if (tid == 0) out[b] = red[0];
}

extern "C" void kernel_launch(void* const* d_in, const int* in_sizes, int n_in,
                              void* d_out, int out_size) {
    const float* mu_p = (const float*)d_in[0];
    const float* lv_p = (const float*)d_in[1];
    const float* mu_g = (const float*)d_in[2];
    const float* lv_g = (const float*)d_in[3];
    float* out = (float*)d_out;

    dim3 grid(NITILE, NB, NCH);  // 16 x 8 x 8 = 1024 CTAs
    ck_main<<<grid, 128>>>(mu_p, lv_p, mu_g, lv_g);
    ck_reduce<<<NB, 256>>>(out);
}

// round 4
// speedup vs baseline: 2.4662x; 1.1998x over previous
#include <cuda_runtime.h>
#include <float.h>

// ChamferLossKL: bs=8, n=2048, d=4 — role-deduped single-pass + parallel reduce.
// S_ij = sum_d A_id*iv_jd + sum_d mu_id*w_jd   (computed ONCE per pair)
//   A = exp(la)+mu_a^2, iv = exp(-lb), w = -2*mu_b*iv
// KL_ij = 0.5*(S + csb_j + ca_i) - 2,  csb = cb+sb, ca = -sa
// rowmin_i = min_j (S + csb_j)  -> rowres_i = 0.5*rowmin + 0.5*ca_i - 2
// colmin_j = min_i (S + ca_i)   -> colres_j = 0.5*colmin + 0.5*csb_j - 2

#define NB 8
#define NP 2048
#define NPAIR 1024
#define ITILE 128
#define NITILE (NP/ITILE)   // 16
#define CHJ 256
#define CHP (CHJ/2)         // 128
#define NCH (NP/CHJ)        // 8
#define NGRP (CHP/32)       // 4
#define NS 8                // reduce slices per batch

typedef unsigned long long ull;

__device__ __forceinline__ ull ffma2(ull a, ull b, ull c) {
    ull d; asm("fma.rn.f32x2 %0, %1, %2, %3;" : "=l"(d) : "l"(a), "l"(b), "l"(c));
    return d;
}
__device__ __forceinline__ ull fmul2(ull a, ull b) {
    ull d; asm("mul.rn.f32x2 %0, %1, %2;" : "=l"(d) : "l"(a), "l"(b));
    return d;
}
__device__ __forceinline__ ull fadd2(ull a, ull b) {
    ull d; asm("add.rn.f32x2 %0, %1, %2;" : "=l"(d) : "l"(a), "l"(b));
    return d;
}
__device__ __forceinline__ ull packdup(float x) {
    ull d; asm("mov.b64 %0, {%1, %1};" : "=l"(d) : "f"(x));
    return d;
}
__device__ __forceinline__ ull pk(float lo, float hi) {
    ull d; asm("mov.b64 %0, {%1, %2};" : "=l"(d) : "f"(lo), "f"(hi));
    return d;
}
__device__ __forceinline__ void unpk(ull v, float& lo, float& hi) {
    asm("mov.b64 {%0, %1}, %2;" : "=f"(lo), "=f"(hi) : "l"(v));
}
__device__ __forceinline__ ull min2(ull a, ull b) {
    float al, ah, bl, bh;
    unpk(a, al, ah); unpk(b, bl, bh);
    return pk(fminf(al, bl), fminf(ah, bh));
}
__device__ __forceinline__ void lds_v2(ull& a, ull& b, unsigned int addr) {
    asm volatile("ld.shared.v2.u64 {%0, %1}, [%2];" : "=l"(a), "=l"(b) : "r"(addr));
}
__device__ __forceinline__ ull lds_1(unsigned int addr) {
    ull a; asm volatile("ld.shared.u64 %0, [%1];" : "=l"(a) : "r"(addr));
    return a;
}

template<int M, int H>
__device__ __forceinline__ void bstep(ull* cv, int lane) {
    bool up = (lane & M) != 0;
#pragma unroll
    for (int k = 0; k < H; k++) {
        ull sb = up ? cv[k] : cv[k + H];
        ull rc = __shfl_xor_sync(0xffffffffu, sb, M);
        ull kp = up ? cv[k + H] : cv[k];
        cv[k] = min2(kp, rc);
    }
}

// ---- scratch ----
__device__ ull    g_colpart[NB * NITILE * NPAIR];
__device__ float  g_rowpart[NB * NCH * NP];
__device__ float2 g_csb[NB * NPAIR];

// grid (NITILE, NB, NCH), block 128.
__global__ __launch_bounds__(128, 1) void ck_main(const float* __restrict__ mu_p,
                                                  const float* __restrict__ lv_p,
                                                  const float* __restrict__ mu_g,
                                                  const float* __restrict__ lv_g,
                                                  float* __restrict__ out) {
    __shared__ float4 s_stream[CHP * 5];
    __shared__ ull    s_col[4 * CHP];

    int tid  = threadIdx.x;
    int lane = tid & 31;
    int w    = tid >> 5;
    int b     = blockIdx.y;
    int itile = blockIdx.x;
    int ch    = blockIdx.z;

    if (itile == 0 && ch == 0 && tid == 0) out[b] = 0.0f;  // seed for atomics

    int i = itile * ITILE + tid;
    float4 mp = reinterpret_cast<const float4*>(mu_p)[b * NP + i];
    float4 lp = reinterpret_cast<const float4*>(lv_p)[b * NP + i];
    float Ax = expf(lp.x) + mp.x * mp.x;
    float Ay = expf(lp.y) + mp.y * mp.y;
    float Az = expf(lp.z) + mp.z * mp.z;
    float Aw = expf(lp.w) + mp.w * mp.w;
    float ca = -(lp.x + lp.y + lp.z + lp.w);
    ull cA0 = packdup(Ax), cA1 = packdup(Ay), cA2 = packdup(Az), cA3 = packdup(Aw);
    ull cM0 = packdup(mp.x), cM1 = packdup(mp.y), cM2 = packdup(mp.z), cM3 = packdup(mp.w);
    ull negsa2 = packdup(ca);

    {
        int j0 = ch * CHJ + 2 * tid;
        float4 mg0 = reinterpret_cast<const float4*>(mu_g)[b * NP + j0];
        float4 lg0 = reinterpret_cast<const float4*>(lv_g)[b * NP + j0];
        float4 mg1 = reinterpret_cast<const float4*>(mu_g)[b * NP + j0 + 1];
        float4 lg1 = reinterpret_cast<const float4*>(lv_g)[b * NP + j0 + 1];
        float4 iv0, iv1, w0, w1;
        iv0.x = expf(-lg0.x); iv0.y = expf(-lg0.y); iv0.z = expf(-lg0.z); iv0.w = expf(-lg0.w);
        iv1.x = expf(-lg1.x); iv1.y = expf(-lg1.y); iv1.z = expf(-lg1.z); iv1.w = expf(-lg1.w);
        w0.x = -2.f * mg0.x * iv0.x; w0.y = -2.f * mg0.y * iv0.y;
        w0.z = -2.f * mg0.z * iv0.z; w0.w = -2.f * mg0.w * iv0.w;
        w1.x = -2.f * mg1.x * iv1.x; w1.y = -2.f * mg1.y * iv1.y;
        w1.z = -2.f * mg1.z * iv1.z; w1.w = -2.f * mg1.w * iv1.w;
        float csb0 = mg0.x * mg0.x * iv0.x + mg0.y * mg0.y * iv0.y
                   + mg0.z * mg0.z * iv0.z + mg0.w * mg0.w * iv0.w
                   + lg0.x + lg0.y + lg0.z + lg0.w;
        float csb1 = mg1.x * mg1.x * iv1.x + mg1.y * mg1.y * iv1.y
                   + mg1.z * mg1.z * iv1.z + mg1.w * mg1.w * iv1.w
                   + lg1.x + lg1.y + lg1.z + lg1.w;
        s_stream[tid * 5 + 0] = make_float4(iv0.x, iv1.x, iv0.y, iv1.y);
        s_stream[tid * 5 + 1] = make_float4(iv0.z, iv1.z, iv0.w, iv1.w);
        s_stream[tid * 5 + 2] = make_float4(w0.x, w1.x, w0.y, w1.y);
        s_stream[tid * 5 + 3] = make_float4(w0.z, w1.z, w0.w, w1.w);
        s_stream[tid * 5 + 4] = make_float4(csb0, csb1, 0.f, 0.f);
        if (itile == 0)
            g_csb[b * NPAIR + ch * CHP + tid] = make_float2(csb0, csb1);
    }
    __syncthreads();

    unsigned int sbase = (unsigned int)__cvta_generic_to_shared(s_stream);
    float minr0 = FLT_MAX, minr1 = FLT_MAX;

    for (int g = 0; g < NGRP; g++) {
        ull cv[32];
        unsigned int ad = sbase + g * 32 * 80;
#pragma unroll
        for (int p = 0; p < 32; p++) {
            ull q0, q1, q2, q3, r0, r1, r2, r3;
            lds_v2(q0, q1, ad);
            lds_v2(q2, q3, ad + 16);
            lds_v2(r0, r1, ad + 32);
            lds_v2(r2, r3, ad + 48);
            ull csb = lds_1(ad + 64);
            ull acc = fmul2(cA0, q0);
            acc = ffma2(cA1, q1, acc);
            acc = ffma2(cA2, q2, acc);
            acc = ffma2(cA3, q3, acc);
            acc = ffma2(cM0, r0, acc);
            acc = ffma2(cM1, r1, acc);
            acc = ffma2(cM2, r2, acc);
            acc = ffma2(cM3, r3, acc);
            ull rowv = fadd2(acc, csb);
            float lo, hi; unpk(rowv, lo, hi);
            minr0 = fminf(minr0, lo);
            minr1 = fminf(minr1, hi);
            cv[p] = fadd2(acc, negsa2);
            ad += 80;
        }
        bstep<16, 16>(cv, lane);
        bstep<8, 8>(cv, lane);
        bstep<4, 4>(cv, lane);
        bstep<2, 2>(cv, lane);
        bstep<1, 1>(cv, lane);
        s_col[w * CHP + g * 32 + lane] = cv[0];
    }

    float rres = 0.5f * fminf(minr0, minr1) + 0.5f * ca - 2.0f;
    g_rowpart[(b * NCH + ch) * NP + i] = rres;

    __syncthreads();
    {
        int e = tid;
        ull m = min2(min2(s_col[e], s_col[CHP + e]),
                     min2(s_col[2 * CHP + e], s_col[3 * CHP + e]));
        g_colpart[(b * NITILE + itile) * NPAIR + ch * CHP + e] = m;
    }
}

// grid (NB, NS) = 64 CTAs, 256 threads. Slice s: 256 i-rows + 128 j-pairs.
__global__ __launch_bounds__(256) void ck_reduce(float* __restrict__ out) {
    int b = blockIdx.x;
    int s = blockIdx.y;
    int tid = threadIdx.x;

    float sum = 0.f;

    // row side: one i per thread, min over NCH chunks (independent LDGs, MLP=8)
    {
        int i = s * 256 + tid;
        const float* rp = &g_rowpart[b * NCH * NP + i];
        float v0 = rp[0 * NP], v1 = rp[1 * NP], v2 = rp[2 * NP], v3 = rp[3 * NP];
        float v4 = rp[4 * NP], v5 = rp[5 * NP], v6 = rp[6 * NP], v7 = rp[7 * NP];
        sum += fminf(fminf(fminf(v0, v1), fminf(v2, v3)),
                     fminf(fminf(v4, v5), fminf(v6, v7)));
    }

    // col side: 2 threads per pair, 8 itiles each, shfl-merge
    {
        int e = s * 128 + (tid >> 1);
        int h = tid & 1;
        const ull* cp = &g_colpart[b * NITILE * NPAIR + e];
        ull m = cp[(h * 8 + 0) * NPAIR];
#pragma unroll
        for (int it = 1; it < 8; it++)
            m = min2(m, cp[(h * 8 + it) * NPAIR]);
        ull other = __shfl_xor_sync(0xffffffffu, m, 1);
        m = min2(m, other);
        if (h == 0) {
            float lo, hi; unpk(m, lo, hi);
            float2 cs = g_csb[b * NPAIR + e];
            sum += 0.5f * lo + 0.5f * cs.x - 2.0f;
            sum += 0.5f * hi + 0.5f * cs.y - 2.0f;
        }
    }

    // CTA reduce + atomic
    __shared__ float red[256];
    red[tid] = sum;
    __syncthreads();
    for (int st = 128; st > 0; st >>= 1) {
        if (tid < st) red[tid] += red[tid + st];
        __syncthreads();
    }
    if (tid == 0) atomicAdd(&out[b], red[0]);
}

extern "C" void kernel_launch(void* const* d_in, const int* in_sizes, int n_in,
                              void* d_out, int out_size) {
    const float* mu_p = (const float*)d_in[0];
    const float* lv_p = (const float*)d_in[1];
    const float* mu_g = (const float*)d_in[2];
    const float* lv_g = (const float*)d_in[3];
    float* out = (float*)d_out;

    dim3 grid(NITILE, NB, NCH);  // 1024 CTAs
    ck_main<<<grid, 128>>>(mu_p, lv_p, mu_g, lv_g, out);

    dim3 rgrid(NB, NS);          // 64 CTAs
    ck_reduce<<<rgrid, 256>>>(out);
}